// round 6
// baseline (speedup 1.0000x reference)
#include <cuda_runtime.h>
#include <math.h>
#include <stdint.h>

#define T_SEQ 4096
#define EMB   512
#define NHEAD 8
#define HDIM  64
#define QSCALE 0.18033688011112042f   // (1/8) * log2(e): softmax via ex2

// Scratch (allocation-free rule)
__device__ __align__(1024) float g_x [T_SEQ * EMB];
__device__ __align__(1024) float g_w [4 * EMB * EMB];
__device__ __align__(1024) float g_Q [T_SEQ * EMB];
__device__ __align__(1024) float g_K [T_SEQ * EMB];
__device__ __align__(1024) float g_Vt[EMB * T_SEQ];   // [n=h*64+d][t]
__device__ __align__(1024) float g_att[T_SEQ * EMB];

// ----------------------------------------------------------------- helpers
__device__ __forceinline__ uint32_t s2u(const void* p) {
    uint32_t a;
    asm("{ .reg .u64 t; cvta.to.shared.u64 t, %1; cvt.u32.u64 %0, t; }"
        : "=r"(a) : "l"(p));
    return a;
}
__device__ __forceinline__ float tf32r(float x) {
    uint32_t u;
    asm("cvt.rna.tf32.f32 %0, %1;" : "=r"(u) : "f"(x));
    return __uint_as_float(u);
}
__device__ __forceinline__ float ex2f(float x) {
    float y;
    asm("ex2.approx.ftz.f32 %0, %1;" : "=f"(y) : "f"(x));
    return y;
}
__device__ __forceinline__ void ldsm4(uint32_t* r, uint32_t addr) {
    asm volatile("ldmatrix.sync.aligned.m8n8.x4.shared.b16 {%0,%1,%2,%3}, [%4];"
                 : "=r"(r[0]), "=r"(r[1]), "=r"(r[2]), "=r"(r[3]) : "r"(addr));
}
__device__ __forceinline__ void mma8(float* c, const uint32_t* a,
                                     uint32_t b0, uint32_t b1) {
    asm volatile(
        "mma.sync.aligned.m16n8k8.row.col.f32.tf32.tf32.f32 "
        "{%0,%1,%2,%3}, {%4,%5,%6,%7}, {%8,%9}, {%0,%1,%2,%3};"
        : "+f"(c[0]), "+f"(c[1]), "+f"(c[2]), "+f"(c[3])
        : "r"(a[0]), "r"(a[1]), "r"(a[2]), "r"(a[3]), "r"(b0), "r"(b1));
}
__device__ __forceinline__ uint32_t swz(uint32_t base, int rowBytes, int r, int kc) {
    return base + (uint32_t)r * rowBytes + ((uint32_t)(kc ^ (r & 7)) << 4);
}
__device__ __forceinline__ uint32_t fragAddr(uint32_t base, int rowBytes,
                                             int r0, int kc0, int lane) {
    int r  = r0 + (lane & 7) + ((lane >> 3) & 1) * 8;
    int kc = kc0 + (lane >> 4);
    return swz(base, rowBytes, r, kc);
}

#define CP16(dst, src)                                                          \
    asm volatile("{ .reg .u64 g; cvta.to.global.u64 g, %1;"                    \
                 " cp.async.cg.shared.global [%0], [g], 16; }"                  \
                 :: "r"(dst), "l"(src) : "memory")
#define CP_COMMIT()  asm volatile("cp.async.commit_group;" ::: "memory")
#define CP_WAITN(N)  asm volatile("cp.async.wait_group %0;" :: "n"(N) : "memory")

// ----------------------------------------------------------------- fused round
__global__ void round_all(const float* __restrict__ x,
                          const float* __restrict__ wq, const float* __restrict__ wk,
                          const float* __restrict__ wv, const float* __restrict__ wo,
                          float* __restrict__ dx, float* __restrict__ dw) {
    int i = blockIdx.x * 256 + threadIdx.x;          // grid 3072 -> 786432 float4s
    const float4* src;
    float4* dst;
    int off;
    if (i < 524288) {
        src = (const float4*)x; dst = (float4*)dx; off = i;
    } else {
        int j = i - 524288;
        int w = j >> 16;                             // 0..3
        off = j & 65535;
        const float* ws = (w == 0) ? wq : (w == 1) ? wk : (w == 2) ? wv : wo;
        src = (const float4*)ws;
        dst = (float4*)(dw + (size_t)w * EMB * EMB);
    }
    float4 v = src[off];
    v.x = tf32r(v.x); v.y = tf32r(v.y); v.z = tf32r(v.z); v.w = tf32r(v.w);
    dst[off] = v;
}

// ----------------------------------------------------------------- GEMM core
// C[4096,512] = A[4096,512] @ B[512,512]^T.  BM=128 BN=64 BK=32, 256 thr.
// smem: A dbl 2x16K, B dbl 2x8K = 48K.
#define GSM 49152
__device__ __forceinline__ void gemm_body(const float* A, const float* B, float* C,
                                          float scale, int doRound, int vt,
                                          int m0, int n0, char* sm) {
    const uint32_t sb = s2u(sm);
    const uint32_t sA[2] = {sb, sb + 16384};
    const uint32_t sB[2] = {sb + 32768, sb + 40960};

    const int tid = threadIdx.x, lane = tid & 31, wid = tid >> 5;
    const int wm = wid & 3, wn = wid >> 2;

    auto load = [&](int kt) {
        int buf = kt & 1;
#pragma unroll
        for (int p = 0; p < 4; p++) {
            int idx = p * 256 + tid, r = idx >> 3, kc = idx & 7;
            CP16(swz(sA[buf], 128, r, kc), &A[(size_t)(m0 + r) * EMB + kt * 32 + kc * 4]);
        }
#pragma unroll
        for (int p = 0; p < 2; p++) {
            int idx = p * 256 + tid, r = idx >> 3, kc = idx & 7;
            CP16(swz(sB[buf], 128, r, kc), &B[(size_t)(n0 + r) * EMB + kt * 32 + kc * 4]);
        }
    };

    float acc[2][4][4] = {};
    load(0); CP_COMMIT();

    for (int kt = 0; kt < 16; kt++) {
        if (kt < 15) { load(kt + 1); CP_COMMIT(); CP_WAITN(1); }
        else         { CP_WAITN(0); }
        __syncthreads();
        const uint32_t a0 = sA[kt & 1], b0 = sB[kt & 1];
#pragma unroll
        for (int s = 0; s < 4; s++) {
            uint32_t af[2][4], bf[2][4];
#pragma unroll
            for (int mf = 0; mf < 2; mf++)
                ldsm4(af[mf], fragAddr(a0, 128, wm * 32 + mf * 16, s * 2, lane));
#pragma unroll
            for (int p = 0; p < 2; p++)
                ldsm4(bf[p], fragAddr(b0, 128, wn * 32 + p * 16, s * 2, lane));
#pragma unroll
            for (int mf = 0; mf < 2; mf++)
#pragma unroll
                for (int p = 0; p < 2; p++) {
                    mma8(acc[mf][2 * p],     af[mf], bf[p][0], bf[p][2]);
                    mma8(acc[mf][2 * p + 1], af[mf], bf[p][1], bf[p][3]);
                }
        }
        __syncthreads();
    }

#pragma unroll
    for (int mf = 0; mf < 2; mf++) {
        int r0 = m0 + wm * 32 + mf * 16 + (lane >> 2);
#pragma unroll
        for (int nf = 0; nf < 4; nf++) {
            int col = n0 + wn * 32 + nf * 8 + 2 * (lane & 3);
            float v0 = acc[mf][nf][0] * scale, v1 = acc[mf][nf][1] * scale;
            float v2 = acc[mf][nf][2] * scale, v3 = acc[mf][nf][3] * scale;
            if (doRound) { v0 = tf32r(v0); v1 = tf32r(v1); v2 = tf32r(v2); v3 = tf32r(v3); }
            if (!vt) {
                *(float2*)&C[(size_t)r0 * EMB + col]       = make_float2(v0, v1);
                *(float2*)&C[(size_t)(r0 + 8) * EMB + col] = make_float2(v2, v3);
            } else {
                C[(size_t)col * T_SEQ + r0]           = v0;
                C[(size_t)(col + 1) * T_SEQ + r0]     = v1;
                C[(size_t)col * T_SEQ + r0 + 8]       = v2;
                C[(size_t)(col + 1) * T_SEQ + r0 + 8] = v3;
            }
        }
    }
}

// Fused QKV: blockIdx.x: [0,8) -> Q, [8,16) -> K, [16,24) -> V(transposed out)
__global__ __launch_bounds__(256, 2) void qkv_gemm(const float* __restrict__ A,
                                                   const float* __restrict__ W,
                                                   float* __restrict__ Cq,
                                                   float* __restrict__ Ck,
                                                   float* __restrict__ Cv) {
    extern __shared__ __align__(1024) char sm[];
    int which = blockIdx.x >> 3;
    int n0 = (blockIdx.x & 7) * 64;
    int m0 = blockIdx.y * 128;
    const float* B = W + (size_t)which * EMB * EMB;
    float* C = (which == 0) ? Cq : (which == 1) ? Ck : Cv;
    float scale = (which == 0) ? QSCALE : 1.0f;
    gemm_body(A, B, C, scale, 1, which == 2, m0, n0, sm);
}

__global__ __launch_bounds__(256, 2) void gemm_tc(const float* __restrict__ A,
                                                  const float* __restrict__ B,
                                                  float* __restrict__ C,
                                                  float scale, int doRound, int vt) {
    extern __shared__ __align__(1024) char sm[];
    gemm_body(A, B, C, scale, doRound, vt, blockIdx.y * 128, blockIdx.x * 64, sm);
}

// ----------------------------------------------------------------- attention
// CTA: 128 q x 1 head, 64 key tiles of 64 keys, 256 thr, 1 CTA/SM (255-reg budget).
// Q fragments register-cached for the whole kernel. P never touches smem: S
// accumulators are exp'd + tf32-rounded + shuffle-transposed into tf32 A-frags
// in registers; each wn-group runs PV over its own 32-key half of V and the
// two partial (O, l) pairs are combined once at the end through smem.
// smem: Q 32K | K dbl 32K | V 16K | Ored 34K | lsum 512B
#define RED_OFF  81920
#define RED_RB   272
#define LSUM_OFF (RED_OFF + 128 * RED_RB)
#define ASMEM    (LSUM_OFF + 512)
__global__ __launch_bounds__(256, 1) void attn_tc(const float* __restrict__ Q,
                                                  const float* __restrict__ K,
                                                  const float* __restrict__ Vt,
                                                  float* __restrict__ O) {
    extern __shared__ __align__(1024) char sm[];
    const uint32_t sb = s2u(sm);
    const uint32_t sQ = sb;
    const uint32_t sK[2] = {sb + 32768, sb + 49152};
    const uint32_t sV = sb + 65536;
    float* red  = (float*)(sm + RED_OFF);
    float* lsum = (float*)(sm + LSUM_OFF);

    const int tid = threadIdx.x, lane = tid & 31, wid = tid >> 5;
    const int wm = wid & 3, wn = wid >> 2;
    const int h = blockIdx.y, q0 = blockIdx.x * 128;

    auto loadK = [&](int t) {
        int k0 = t * 64;
        uint32_t base = sK[t & 1];
#pragma unroll
        for (int p = 0; p < 4; p++) {
            int idx = p * 256 + tid, r = idx >> 4, kc = idx & 15;
            CP16(swz(base, 256, r, kc), &K[(size_t)(k0 + r) * EMB + h * HDIM + kc * 4]);
        }
    };
    auto loadV = [&](int t) {
#pragma unroll
        for (int p = 0; p < 4; p++) {
            int idx = p * 256 + tid, r = idx >> 4, kc = idx & 15;
            CP16(swz(sV, 256, r, kc), &Vt[(size_t)(h * HDIM + r) * T_SEQ + t * 64 + kc * 4]);
        }
    };

    // prologue: {Q, K0} one group
#pragma unroll
    for (int p = 0; p < 8; p++) {
        int idx = p * 256 + tid, r = idx >> 4, kc = idx & 15;
        CP16(swz(sQ, 256, r, kc), &Q[(size_t)(q0 + r) * EMB + h * HDIM + kc * 4]);
    }
    loadK(0); CP_COMMIT();
    CP_WAITN(0);
    __syncthreads();

    // register-cache Q fragments: m32 x k64 per warp = 64 regs
    uint32_t qf[8][2][4];
#pragma unroll
    for (int s = 0; s < 8; s++)
#pragma unroll
        for (int mf = 0; mf < 2; mf++)
            ldsm4(qf[s][mf], fragAddr(sQ, 256, wm * 32 + mf * 16, s * 2, lane));

    float oacc[2][8][4] = {};
    float la[4] = {};

    const int j  = lane & 3;
    const int s0 = (lane & ~3) | (j >> 1);
    const int s1 = s0 + 2;
    const bool odd = lane & 1;

    for (int t = 0; t < 64; t++) {
        loadV(t); CP_COMMIT();
        if (t < 63) { loadK(t + 1); CP_COMMIT(); CP_WAITN(2); }   // K(t) ready
        else        { CP_WAITN(1); }                               // K(63) ready
        __syncthreads();

        // --- S = Q K(t)^T (log2 domain) ---
        float sacc[2][4][4] = {};
        const uint32_t kb = sK[t & 1];
#pragma unroll
        for (int s = 0; s < 8; s++) {
            uint32_t kf[2][4];
            ldsm4(kf[0], fragAddr(kb, 256, wn * 32,      s * 2, lane));
            ldsm4(kf[1], fragAddr(kb, 256, wn * 32 + 16, s * 2, lane));
#pragma unroll
            for (int mf = 0; mf < 2; mf++) {
                mma8(sacc[mf][0], qf[s][mf], kf[0][0], kf[0][2]);
                mma8(sacc[mf][1], qf[s][mf], kf[0][1], kf[0][3]);
                mma8(sacc[mf][2], qf[s][mf], kf[1][0], kf[1][2]);
                mma8(sacc[mf][3], qf[s][mf], kf[1][1], kf[1][3]);
            }
        }

        // --- P = 2^S, tf32-round, l partials; shuffle-transpose C->A frags ---
        uint32_t aP[2][4][4];
#pragma unroll
        for (int mf = 0; mf < 2; mf++) {
            float r0s = 0.0f, r1s = 0.0f;
#pragma unroll
            for (int nf = 0; nf < 4; nf++) {
                float e0 = tf32r(ex2f(sacc[mf][nf][0]));
                float e1 = tf32r(ex2f(sacc[mf][nf][1]));
                float e2 = tf32r(ex2f(sacc[mf][nf][2]));
                float e3 = tf32r(ex2f(sacc[mf][nf][3]));
                r0s += e0 + e1;
                r1s += e2 + e3;
                // C layout (row, 2j/2j+1) -> tf32 A-frag (row, k=j | j+4)
                float t00 = __shfl_sync(0xffffffffu, e0, s0);
                float t01 = __shfl_sync(0xffffffffu, e1, s0);
                float t10 = __shfl_sync(0xffffffffu, e2, s0);
                float t11 = __shfl_sync(0xffffffffu, e3, s0);
                float u00 = __shfl_sync(0xffffffffu, e0, s1);
                float u01 = __shfl_sync(0xffffffffu, e1, s1);
                float u10 = __shfl_sync(0xffffffffu, e2, s1);
                float u11 = __shfl_sync(0xffffffffu, e3, s1);
                aP[mf][nf][0] = __float_as_uint(odd ? t01 : t00);
                aP[mf][nf][1] = __float_as_uint(odd ? t11 : t10);
                aP[mf][nf][2] = __float_as_uint(odd ? u01 : u00);
                aP[mf][nf][3] = __float_as_uint(odd ? u11 : u10);
            }
            r0s += __shfl_xor_sync(0xffffffffu, r0s, 1);
            r0s += __shfl_xor_sync(0xffffffffu, r0s, 2);
            r1s += __shfl_xor_sync(0xffffffffu, r1s, 1);
            r1s += __shfl_xor_sync(0xffffffffu, r1s, 2);
            la[mf * 2]     += r0s;
            la[mf * 2 + 1] += r1s;
        }

        if (t < 63) CP_WAITN(1); else CP_WAITN(0);   // V(t) ready
        __syncthreads();

        // --- O += P V(t): this wn-group's 32-key half ---
#pragma unroll
        for (int nf = 0; nf < 4; nf++) {
            int kc0 = wn * 8 + nf * 2;
            uint32_t bf[4][4];
#pragma unroll
            for (int p = 0; p < 4; p++)
                ldsm4(bf[p], fragAddr(sV, 256, p * 16, kc0, lane));
#pragma unroll
            for (int mf = 0; mf < 2; mf++)
#pragma unroll
                for (int p = 0; p < 4; p++) {
                    mma8(oacc[mf][2 * p],     aP[mf][nf], bf[p][0], bf[p][2]);
                    mma8(oacc[mf][2 * p + 1], aP[mf][nf], bf[p][1], bf[p][3]);
                }
        }
        __syncthreads();   // V / K-buf reuse safe
    }

    // --- combine wn halves: wn0 publishes partial O and l; wn1 finalizes ---
    if (wn == 0) {
#pragma unroll
        for (int mf = 0; mf < 2; mf++) {
            int r = wm * 32 + mf * 16 + (lane >> 2);
#pragma unroll
            for (int df = 0; df < 8; df++) {
                int col = df * 8 + 2 * (lane & 3);
                *(float2*)((char*)red + r * RED_RB + col * 4) =
                    make_float2(oacc[mf][df][0], oacc[mf][df][1]);
                *(float2*)((char*)red + (r + 8) * RED_RB + col * 4) =
                    make_float2(oacc[mf][df][2], oacc[mf][df][3]);
            }
        }
        if ((lane & 3) == 0) {
            int r = wm * 32 + (lane >> 2);
            lsum[r]      = la[0];
            lsum[r + 8]  = la[1];
            lsum[r + 16] = la[2];
            lsum[r + 24] = la[3];
        }
    }
    __syncthreads();
    if (wn == 1) {
#pragma unroll
        for (int mf = 0; mf < 2; mf++) {
            int r = wm * 32 + mf * 16 + (lane >> 2);
            float li0 = 1.0f / (lsum[r]     + la[mf * 2]);
            float li1 = 1.0f / (lsum[r + 8] + la[mf * 2 + 1]);
#pragma unroll
            for (int df = 0; df < 8; df++) {
                int col = df * 8 + 2 * (lane & 3);
                float2 p0 = *(float2*)((char*)red + r * RED_RB + col * 4);
                float2 p1 = *(float2*)((char*)red + (r + 8) * RED_RB + col * 4);
                float2 v0 = make_float2(tf32r((p0.x + oacc[mf][df][0]) * li0),
                                        tf32r((p0.y + oacc[mf][df][1]) * li0));
                float2 v1 = make_float2(tf32r((p1.x + oacc[mf][df][2]) * li1),
                                        tf32r((p1.y + oacc[mf][df][3]) * li1));
                *(float2*)&O[(size_t)(q0 + r) * EMB + h * HDIM + col]     = v0;
                *(float2*)&O[(size_t)(q0 + r + 8) * EMB + h * HDIM + col] = v1;
            }
        }
    }
}

// ----------------------------------------------------------------- launch
extern "C" void kernel_launch(void* const* d_in, const int* in_sizes, int n_in,
                              void* d_out, int out_size) {
    const float* x  = (const float*)d_in[0];
    const float* wq = (const float*)d_in[1];
    const float* wk = (const float*)d_in[2];
    const float* wv = (const float*)d_in[3];
    const float* wo = (const float*)d_in[4];
    float* out = (float*)d_out;

    float *px, *pw, *pQ, *pK, *pVt, *pA;
    cudaGetSymbolAddress((void**)&px, g_x);
    cudaGetSymbolAddress((void**)&pw, g_w);
    cudaGetSymbolAddress((void**)&pQ, g_Q);
    cudaGetSymbolAddress((void**)&pK, g_K);
    cudaGetSymbolAddress((void**)&pVt, g_Vt);
    cudaGetSymbolAddress((void**)&pA, g_att);

    cudaFuncSetAttribute(qkv_gemm, cudaFuncAttributeMaxDynamicSharedMemorySize, GSM);
    cudaFuncSetAttribute(gemm_tc, cudaFuncAttributeMaxDynamicSharedMemorySize, GSM);
    cudaFuncSetAttribute(attn_tc, cudaFuncAttributeMaxDynamicSharedMemorySize, ASMEM);

    round_all<<<3072, 256>>>(x, wq, wk, wv, wo, px, pw);

    qkv_gemm<<<dim3(24, 32), 256, GSM>>>(px, pw, pQ, pK, pVt);

    dim3 ga(T_SEQ / 128, NHEAD);       // (32, 8)
    attn_tc<<<ga, 256, ASMEM>>>(pQ, pK, pVt, pA);

    gemm_tc<<<dim3(8, 32), 256, GSM>>>(pA, pw + 3 * EMB * EMB, out, 1.0f, 0, 0);
}

// round 7
// speedup vs baseline: 2.0773x; 2.0773x over previous
#include <cuda_runtime.h>
#include <cuda_fp16.h>
#include <math.h>
#include <stdint.h>

#define T_SEQ 4096
#define EMB   512
#define NHEAD 8
#define HDIM  64
#define QSCALE 0.18033688011112042f   // (1/8) * log2(e): softmax via ex2

// Scratch (allocation-free rule) — all fp16 intermediates
__device__ __align__(1024) __half g_x [T_SEQ * EMB];
__device__ __align__(1024) __half g_w [4 * EMB * EMB];
__device__ __align__(1024) __half g_Q [T_SEQ * EMB];
__device__ __align__(1024) __half g_K [T_SEQ * EMB];
__device__ __align__(1024) __half g_Vt[EMB * T_SEQ];   // [n=h*64+d][t]
__device__ __align__(1024) __half g_att[T_SEQ * EMB];

// ----------------------------------------------------------------- helpers
__device__ __forceinline__ uint32_t s2u(const void* p) {
    uint32_t a;
    asm("{ .reg .u64 t; cvta.to.shared.u64 t, %1; cvt.u32.u64 %0, t; }"
        : "=r"(a) : "l"(p));
    return a;
}
__device__ __forceinline__ uint32_t packh2(float lo, float hi) {
    __half2 h = __floats2half2_rn(lo, hi);
    return *(uint32_t*)&h;
}
__device__ __forceinline__ float ex2f(float x) {
    float y;
    asm("ex2.approx.ftz.f32 %0, %1;" : "=f"(y) : "f"(x));
    return y;
}
__device__ __forceinline__ void ldsm4(uint32_t* r, uint32_t addr) {
    asm volatile("ldmatrix.sync.aligned.m8n8.x4.shared.b16 {%0,%1,%2,%3}, [%4];"
                 : "=r"(r[0]), "=r"(r[1]), "=r"(r[2]), "=r"(r[3]) : "r"(addr));
}
__device__ __forceinline__ void mma16(float* c, const uint32_t* a,
                                      uint32_t b0, uint32_t b1) {
    asm volatile(
        "mma.sync.aligned.m16n8k16.row.col.f32.f16.f16.f32 "
        "{%0,%1,%2,%3}, {%4,%5,%6,%7}, {%8,%9}, {%0,%1,%2,%3};"
        : "+f"(c[0]), "+f"(c[1]), "+f"(c[2]), "+f"(c[3])
        : "r"(a[0]), "r"(a[1]), "r"(a[2]), "r"(a[3]), "r"(b0), "r"(b1));
}
// 16B-chunk XOR swizzle (8 chunks per 128B row of 64 halves)
__device__ __forceinline__ uint32_t swz(uint32_t base, int rowBytes, int r, int kc) {
    return base + (uint32_t)r * rowBytes + ((uint32_t)(kc ^ (r & 7)) << 4);
}
__device__ __forceinline__ uint32_t fragAddr(uint32_t base, int rowBytes,
                                             int r0, int kc0, int lane) {
    int r  = r0 + (lane & 7) + ((lane >> 3) & 1) * 8;
    int kc = kc0 + (lane >> 4);
    return swz(base, rowBytes, r, kc);
}

#define CP16(dst, src)                                                          \
    asm volatile("{ .reg .u64 g; cvta.to.global.u64 g, %1;"                    \
                 " cp.async.cg.shared.global [%0], [g], 16; }"                  \
                 :: "r"(dst), "l"(src) : "memory")
#define CP_COMMIT()  asm volatile("cp.async.commit_group;" ::: "memory")
#define CP_WAITN(N)  asm volatile("cp.async.wait_group %0;" :: "n"(N) : "memory")

// ----------------------------------------------------------------- fused round
// x (2M floats) + 4 weights (1M floats) -> fp16-rn, one launch.
__global__ void round_all(const float* __restrict__ x,
                          const float* __restrict__ wq, const float* __restrict__ wk,
                          const float* __restrict__ wv, const float* __restrict__ wo,
                          __half* __restrict__ dx, __half* __restrict__ dw) {
    int i = blockIdx.x * 256 + threadIdx.x;          // 786432 float4 lanes
    const float4* src;
    __half* dstp;
    int off;
    if (i < 524288) {
        src = (const float4*)x; dstp = dx; off = i;
    } else {
        int j = i - 524288;
        int w = j >> 16;                             // 0..3
        off = j & 65535;
        const float* ws = (w == 0) ? wq : (w == 1) ? wk : (w == 2) ? wv : wo;
        src = (const float4*)ws;
        dstp = dw + (size_t)w * EMB * EMB;
    }
    float4 v = src[off];
    uint2 o = make_uint2(packh2(v.x, v.y), packh2(v.z, v.w));
    *((uint2*)dstp + off) = o;
}

// ----------------------------------------------------------------- GEMM core
// C[4096,512] = A[4096,512] @ B[512,512]^T, fp16 in / fp32 acc.
// BM=128 BN=64 BK=64, 256 thr. smem: A dbl 2x16K, B dbl 2x8K = 48K.
#define GSM 49152
__device__ __forceinline__ void gemm_body(const __half* A, const __half* B,
                                          void* Cout, float scale, int mode,
                                          int m0, int n0, char* sm) {
    const uint32_t sb = s2u(sm);
    const uint32_t sA[2] = {sb, sb + 16384};
    const uint32_t sB[2] = {sb + 32768, sb + 40960};

    const int tid = threadIdx.x, lane = tid & 31, wid = tid >> 5;
    const int wm = wid & 3, wn = wid >> 2;

    auto load = [&](int kt) {
        int buf = kt & 1;
#pragma unroll
        for (int p = 0; p < 4; p++) {
            int idx = p * 256 + tid, r = idx >> 3, kc = idx & 7;
            CP16(swz(sA[buf], 128, r, kc), &A[(size_t)(m0 + r) * EMB + kt * 64 + kc * 8]);
        }
#pragma unroll
        for (int p = 0; p < 2; p++) {
            int idx = p * 256 + tid, r = idx >> 3, kc = idx & 7;
            CP16(swz(sB[buf], 128, r, kc), &B[(size_t)(n0 + r) * EMB + kt * 64 + kc * 8]);
        }
    };

    float acc[2][4][4] = {};
    load(0); CP_COMMIT();

    for (int kt = 0; kt < 8; kt++) {
        if (kt < 7) { load(kt + 1); CP_COMMIT(); CP_WAITN(1); }
        else        { CP_WAITN(0); }
        __syncthreads();
        const uint32_t a0 = sA[kt & 1], b0 = sB[kt & 1];
#pragma unroll
        for (int s = 0; s < 4; s++) {               // k16 steps
            uint32_t af[2][4], bf[2][4];
#pragma unroll
            for (int mf = 0; mf < 2; mf++)
                ldsm4(af[mf], fragAddr(a0, 128, wm * 32 + mf * 16, s * 2, lane));
#pragma unroll
            for (int p = 0; p < 2; p++)
                ldsm4(bf[p], fragAddr(b0, 128, wn * 32 + p * 16, s * 2, lane));
#pragma unroll
            for (int mf = 0; mf < 2; mf++)
#pragma unroll
                for (int p = 0; p < 2; p++) {
                    mma16(acc[mf][2 * p],     af[mf], bf[p][0], bf[p][2]);
                    mma16(acc[mf][2 * p + 1], af[mf], bf[p][1], bf[p][3]);
                }
        }
        __syncthreads();
    }

#pragma unroll
    for (int mf = 0; mf < 2; mf++) {
        int r0 = m0 + wm * 32 + mf * 16 + (lane >> 2);
#pragma unroll
        for (int nf = 0; nf < 4; nf++) {
            int col = n0 + wn * 32 + nf * 8 + 2 * (lane & 3);
            float v0 = acc[mf][nf][0] * scale, v1 = acc[mf][nf][1] * scale;
            float v2 = acc[mf][nf][2] * scale, v3 = acc[mf][nf][3] * scale;
            if (mode == 0) {                         // half, row-major
                __half* C = (__half*)Cout;
                *(uint32_t*)&C[(size_t)r0 * EMB + col]       = packh2(v0, v1);
                *(uint32_t*)&C[(size_t)(r0 + 8) * EMB + col] = packh2(v2, v3);
            } else if (mode == 1) {                  // half, transposed (Vt)
                __half* C = (__half*)Cout;
                C[(size_t)col * T_SEQ + r0]           = __float2half_rn(v0);
                C[(size_t)(col + 1) * T_SEQ + r0]     = __float2half_rn(v1);
                C[(size_t)col * T_SEQ + r0 + 8]       = __float2half_rn(v2);
                C[(size_t)(col + 1) * T_SEQ + r0 + 8] = __float2half_rn(v3);
            } else {                                 // fp32 final output
                float* C = (float*)Cout;
                *(float2*)&C[(size_t)r0 * EMB + col]       = make_float2(v0, v1);
                *(float2*)&C[(size_t)(r0 + 8) * EMB + col] = make_float2(v2, v3);
            }
        }
    }
}

// Fused QKV: blockIdx.x: [0,8) -> Q, [8,16) -> K, [16,24) -> V(transposed out)
__global__ __launch_bounds__(256, 2) void qkv_gemm(const __half* __restrict__ A,
                                                   const __half* __restrict__ W,
                                                   __half* __restrict__ Cq,
                                                   __half* __restrict__ Ck,
                                                   __half* __restrict__ Cv) {
    extern __shared__ __align__(1024) char sm[];
    int which = blockIdx.x >> 3;
    int n0 = (blockIdx.x & 7) * 64;
    int m0 = blockIdx.y * 128;
    const __half* B = W + (size_t)which * EMB * EMB;
    __half* C = (which == 0) ? Cq : (which == 1) ? Ck : Cv;
    float scale = (which == 0) ? QSCALE : 1.0f;
    gemm_body(A, B, C, scale, (which == 2) ? 1 : 0, m0, n0, sm);
}

__global__ __launch_bounds__(256, 2) void gemm_out(const __half* __restrict__ A,
                                                   const __half* __restrict__ B,
                                                   float* __restrict__ C) {
    extern __shared__ __align__(1024) char sm[];
    gemm_body(A, B, C, 1.0f, 2, blockIdx.y * 128, blockIdx.x * 64, sm);
}

// ----------------------------------------------------------------- attention
// CTA: 128 q x 1 head, 64 key tiles of 64 keys, 256 thr. All fp16 operands,
// fp32 accum. Q fragments register-cached. K and V double-buffered. P never
// leaves registers: fp32 S-frags convert lane-locally into fp16 A-frags.
// Warp wn handles its own 32-key half of PV (k-split); (O,l) partials merge
// once at the end via smem (reduction buffer overlaps dead K/V space).
// smem: Q 16K | K dbl 16K | V dbl 16K | [red 34K + lsum overlap K/V+pad]
#define RED_OFF  16384
#define RED_RB   272
#define LSUM_OFF (RED_OFF + 128 * RED_RB)   // 51200
#define ASMEM    (LSUM_OFF + 512)           // 51712
__global__ __launch_bounds__(256, 1) void attn_tc(const __half* __restrict__ Q,
                                                  const __half* __restrict__ K,
                                                  const __half* __restrict__ Vt,
                                                  __half* __restrict__ O) {
    extern __shared__ __align__(1024) char sm[];
    const uint32_t sb = s2u(sm);
    const uint32_t sQ = sb;
    const uint32_t sK[2] = {sb + 16384, sb + 24576};
    const uint32_t sV[2] = {sb + 32768, sb + 40960};
    float* red  = (float*)(sm + RED_OFF);
    float* lsum = (float*)(sm + LSUM_OFF);

    const int tid = threadIdx.x, lane = tid & 31, wid = tid >> 5;
    const int wm = wid & 3, wn = wid >> 2;
    const int h = blockIdx.y, q0 = blockIdx.x * 128;

    auto loadK = [&](int t) {
        int k0 = t * 64;
        uint32_t base = sK[t & 1];
#pragma unroll
        for (int p = 0; p < 2; p++) {
            int idx = p * 256 + tid, r = idx >> 3, kc = idx & 7;
            CP16(swz(base, 128, r, kc), &K[(size_t)(k0 + r) * EMB + h * HDIM + kc * 8]);
        }
    };
    auto loadV = [&](int t) {
        uint32_t base = sV[t & 1];
#pragma unroll
        for (int p = 0; p < 2; p++) {
            int idx = p * 256 + tid, r = idx >> 3, kc = idx & 7;
            CP16(swz(base, 128, r, kc), &Vt[(size_t)(h * HDIM + r) * T_SEQ + t * 64 + kc * 8]);
        }
    };

    // prologue: {Q, K0} group, {V0} group
#pragma unroll
    for (int p = 0; p < 4; p++) {
        int idx = p * 256 + tid, r = idx >> 3, kc = idx & 7;
        CP16(swz(sQ, 128, r, kc), &Q[(size_t)(q0 + r) * EMB + h * HDIM + kc * 8]);
    }
    loadK(0); CP_COMMIT();
    loadV(0); CP_COMMIT();
    CP_WAITN(1);               // Q, K0 resident
    __syncthreads();

    // register-cache Q fragments: m32 x k64 per warp = 32 regs
    uint32_t qf[4][2][4];
#pragma unroll
    for (int s = 0; s < 4; s++)
#pragma unroll
        for (int mf = 0; mf < 2; mf++)
            ldsm4(qf[s][mf], fragAddr(sQ, 128, wm * 32 + mf * 16, s * 2, lane));

    float oacc[2][8][4] = {};
    float la[4] = {};

    for (int t = 0; t < 64; t++) {
        if (t < 63) {
            loadK(t + 1); CP_COMMIT();
            loadV(t + 1); CP_COMMIT();
            CP_WAITN(2);       // K(t), V(t) resident
        } else {
            CP_WAITN(0);
        }
        __syncthreads();

        // --- S = Q K(t)^T (log2 domain; Q pre-scaled) ---
        float sacc[2][4][4] = {};
        const uint32_t kb = sK[t & 1];
#pragma unroll
        for (int s = 0; s < 4; s++) {
            uint32_t kf[2][4];
            ldsm4(kf[0], fragAddr(kb, 128, wn * 32,      s * 2, lane));
            ldsm4(kf[1], fragAddr(kb, 128, wn * 32 + 16, s * 2, lane));
#pragma unroll
            for (int mf = 0; mf < 2; mf++) {
                mma16(sacc[mf][0], qf[s][mf], kf[0][0], kf[0][2]);
                mma16(sacc[mf][1], qf[s][mf], kf[0][1], kf[0][3]);
                mma16(sacc[mf][2], qf[s][mf], kf[1][0], kf[1][2]);
                mma16(sacc[mf][3], qf[s][mf], kf[1][1], kf[1][3]);
            }
        }

        // --- P = 2^S -> fp16 A-frags (lane-local pack); l partials ---
        uint32_t aP[2][2][4];
#pragma unroll
        for (int mf = 0; mf < 2; mf++) {
            float r0s = 0.0f, r1s = 0.0f;
#pragma unroll
            for (int nf = 0; nf < 4; nf++) {
                float e0 = ex2f(sacc[mf][nf][0]);
                float e1 = ex2f(sacc[mf][nf][1]);
                float e2 = ex2f(sacc[mf][nf][2]);
                float e3 = ex2f(sacc[mf][nf][3]);
                r0s += e0 + e1;
                r1s += e2 + e3;
                int ks = nf >> 1, hi = (nf & 1) * 2;
                aP[mf][ks][hi]     = packh2(e0, e1);
                aP[mf][ks][hi + 1] = packh2(e2, e3);
            }
            r0s += __shfl_xor_sync(0xffffffffu, r0s, 1);
            r0s += __shfl_xor_sync(0xffffffffu, r0s, 2);
            r1s += __shfl_xor_sync(0xffffffffu, r1s, 1);
            r1s += __shfl_xor_sync(0xffffffffu, r1s, 2);
            la[mf * 2]     += r0s;
            la[mf * 2 + 1] += r1s;
        }
        // NOTE: l sums use fp32 e's; MMA uses fp16-rounded e's. Bias is
        // ~2^-12 relative on l -> ~1e-4 on O, inside budget.

        // --- O += P V(t): this wn-group's 32-key half ---
        const uint32_t vb = sV[t & 1];
#pragma unroll
        for (int ks = 0; ks < 2; ks++) {
            uint32_t bf[4][4];
#pragma unroll
            for (int p = 0; p < 4; p++)
                ldsm4(bf[p], fragAddr(vb, 128, p * 16, wn * 4 + ks * 2, lane));
#pragma unroll
            for (int mf = 0; mf < 2; mf++)
#pragma unroll
                for (int p = 0; p < 4; p++) {
                    mma16(oacc[mf][2 * p],     aP[mf][ks], bf[p][0], bf[p][2]);
                    mma16(oacc[mf][2 * p + 1], aP[mf][ks], bf[p][1], bf[p][3]);
                }
        }
        __syncthreads();       // K/V buffer reuse safe
    }

    // --- combine wn halves: wn0 publishes partial O and l; wn1 finalizes ---
    if (wn == 0) {
#pragma unroll
        for (int mf = 0; mf < 2; mf++) {
            int r = wm * 32 + mf * 16 + (lane >> 2);
#pragma unroll
            for (int df = 0; df < 8; df++) {
                int col = df * 8 + 2 * (lane & 3);
                *(float2*)((char*)red + r * RED_RB + col * 4) =
                    make_float2(oacc[mf][df][0], oacc[mf][df][1]);
                *(float2*)((char*)red + (r + 8) * RED_RB + col * 4) =
                    make_float2(oacc[mf][df][2], oacc[mf][df][3]);
            }
        }
        if ((lane & 3) == 0) {
            int r = wm * 32 + (lane >> 2);
            lsum[r]      = la[0];
            lsum[r + 8]  = la[1];
            lsum[r + 16] = la[2];
            lsum[r + 24] = la[3];
        }
    }
    __syncthreads();
    if (wn == 1) {
#pragma unroll
        for (int mf = 0; mf < 2; mf++) {
            int r = wm * 32 + mf * 16 + (lane >> 2);
            float li0 = 1.0f / (lsum[r]     + la[mf * 2]);
            float li1 = 1.0f / (lsum[r + 8] + la[mf * 2 + 1]);
#pragma unroll
            for (int df = 0; df < 8; df++) {
                int col = df * 8 + 2 * (lane & 3);
                float2 p0 = *(float2*)((char*)red + r * RED_RB + col * 4);
                float2 p1 = *(float2*)((char*)red + (r + 8) * RED_RB + col * 4);
                *(uint32_t*)&O[(size_t)(q0 + r) * EMB + h * HDIM + col] =
                    packh2((p0.x + oacc[mf][df][0]) * li0,
                           (p0.y + oacc[mf][df][1]) * li0);
                *(uint32_t*)&O[(size_t)(q0 + r + 8) * EMB + h * HDIM + col] =
                    packh2((p1.x + oacc[mf][df][2]) * li1,
                           (p1.y + oacc[mf][df][3]) * li1);
            }
        }
    }
}

// ----------------------------------------------------------------- launch
extern "C" void kernel_launch(void* const* d_in, const int* in_sizes, int n_in,
                              void* d_out, int out_size) {
    const float* x  = (const float*)d_in[0];
    const float* wq = (const float*)d_in[1];
    const float* wk = (const float*)d_in[2];
    const float* wv = (const float*)d_in[3];
    const float* wo = (const float*)d_in[4];
    float* out = (float*)d_out;

    __half *px, *pw, *pQ, *pK, *pVt, *pA;
    cudaGetSymbolAddress((void**)&px, g_x);
    cudaGetSymbolAddress((void**)&pw, g_w);
    cudaGetSymbolAddress((void**)&pQ, g_Q);
    cudaGetSymbolAddress((void**)&pK, g_K);
    cudaGetSymbolAddress((void**)&pVt, g_Vt);
    cudaGetSymbolAddress((void**)&pA, g_att);

    cudaFuncSetAttribute(qkv_gemm, cudaFuncAttributeMaxDynamicSharedMemorySize, GSM);
    cudaFuncSetAttribute(gemm_out, cudaFuncAttributeMaxDynamicSharedMemorySize, GSM);
    cudaFuncSetAttribute(attn_tc, cudaFuncAttributeMaxDynamicSharedMemorySize, ASMEM);

    round_all<<<3072, 256>>>(x, wq, wk, wv, wo, px, pw);

    qkv_gemm<<<dim3(24, 32), 256, GSM>>>(px, pw, pQ, pK, pVt);

    dim3 ga(T_SEQ / 128, NHEAD);       // (32, 8)
    attn_tc<<<ga, 256, ASMEM>>>(pQ, pK, pVt, pA);

    gemm_out<<<dim3(8, 32), 256, GSM>>>(pA, pw + 3 * (size_t)EMB * EMB, out);
}

// round 8
// speedup vs baseline: 2.2383x; 1.0775x over previous
#include <cuda_runtime.h>
#include <cuda_fp16.h>
#include <math.h>
#include <stdint.h>

#define T_SEQ 4096
#define EMB   512
#define NHEAD 8
#define HDIM  64
#define QSCALE 0.18033688011112042f   // (1/8) * log2(e): softmax via ex2

// Scratch (allocation-free rule) — all fp16 intermediates
__device__ __align__(1024) __half g_x [T_SEQ * EMB];
__device__ __align__(1024) __half g_w [4 * EMB * EMB];
__device__ __align__(1024) __half g_Q [T_SEQ * EMB];
__device__ __align__(1024) __half g_K [T_SEQ * EMB];
__device__ __align__(1024) __half g_Vt[EMB * T_SEQ];   // [n=h*64+d][t]
__device__ __align__(1024) __half g_att[T_SEQ * EMB];

// ----------------------------------------------------------------- helpers
__device__ __forceinline__ uint32_t s2u(const void* p) {
    uint32_t a;
    asm("{ .reg .u64 t; cvta.to.shared.u64 t, %1; cvt.u32.u64 %0, t; }"
        : "=r"(a) : "l"(p));
    return a;
}
__device__ __forceinline__ uint32_t packh2(float lo, float hi) {
    __half2 h = __floats2half2_rn(lo, hi);
    return *(uint32_t*)&h;
}
__device__ __forceinline__ float ex2f(float x) {
    float y;
    asm("ex2.approx.ftz.f32 %0, %1;" : "=f"(y) : "f"(x));
    return y;
}
__device__ __forceinline__ void ldsm4(uint32_t* r, uint32_t addr) {
    asm volatile("ldmatrix.sync.aligned.m8n8.x4.shared.b16 {%0,%1,%2,%3}, [%4];"
                 : "=r"(r[0]), "=r"(r[1]), "=r"(r[2]), "=r"(r[3]) : "r"(addr));
}
__device__ __forceinline__ void mma16(float* c, const uint32_t* a,
                                      uint32_t b0, uint32_t b1) {
    asm volatile(
        "mma.sync.aligned.m16n8k16.row.col.f32.f16.f16.f32 "
        "{%0,%1,%2,%3}, {%4,%5,%6,%7}, {%8,%9}, {%0,%1,%2,%3};"
        : "+f"(c[0]), "+f"(c[1]), "+f"(c[2]), "+f"(c[3])
        : "r"(a[0]), "r"(a[1]), "r"(a[2]), "r"(a[3]), "r"(b0), "r"(b1));
}
// 16B-chunk XOR swizzle (8 chunks per 128B row of 64 halves)
__device__ __forceinline__ uint32_t swz(uint32_t base, int rowBytes, int r, int kc) {
    return base + (uint32_t)r * rowBytes + ((uint32_t)(kc ^ (r & 7)) << 4);
}
__device__ __forceinline__ uint32_t fragAddr(uint32_t base, int rowBytes,
                                             int r0, int kc0, int lane) {
    int r  = r0 + (lane & 7) + ((lane >> 3) & 1) * 8;
    int kc = kc0 + (lane >> 4);
    return swz(base, rowBytes, r, kc);
}

#define CP16(dst, src)                                                          \
    asm volatile("{ .reg .u64 g; cvta.to.global.u64 g, %1;"                    \
                 " cp.async.cg.shared.global [%0], [g], 16; }"                  \
                 :: "r"(dst), "l"(src) : "memory")
#define CP_COMMIT()  asm volatile("cp.async.commit_group;" ::: "memory")
#define CP_WAITN(N)  asm volatile("cp.async.wait_group %0;" :: "n"(N) : "memory")

// ----------------------------------------------------------------- fused round
__global__ void round_all(const float* __restrict__ x,
                          const float* __restrict__ wq, const float* __restrict__ wk,
                          const float* __restrict__ wv, const float* __restrict__ wo,
                          __half* __restrict__ dx, __half* __restrict__ dw) {
    int i = blockIdx.x * 256 + threadIdx.x;          // 786432 float4 lanes
    const float4* src;
    __half* dstp;
    int off;
    if (i < 524288) {
        src = (const float4*)x; dstp = dx; off = i;
    } else {
        int j = i - 524288;
        int w = j >> 16;                             // 0..3
        off = j & 65535;
        const float* ws = (w == 0) ? wq : (w == 1) ? wk : (w == 2) ? wv : wo;
        src = (const float4*)ws;
        dstp = dw + (size_t)w * EMB * EMB;
    }
    float4 v = src[off];
    uint2 o = make_uint2(packh2(v.x, v.y), packh2(v.z, v.w));
    *((uint2*)dstp + off) = o;
}

// ----------------------------------------------------------------- GEMM core
// C[4096,512] = A[4096,512] @ B[512,512]^T, fp16 in / fp32 acc.
// BM=128 BN=64 BK=64, 256 thr. smem: A dbl 2x16K, B dbl 2x8K = 48K.
#define GSM 49152
__device__ __forceinline__ void gemm_body(const __half* A, const __half* B,
                                          void* Cout, float scale, int mode,
                                          int m0, int n0, char* sm) {
    const uint32_t sb = s2u(sm);
    const uint32_t sA[2] = {sb, sb + 16384};
    const uint32_t sB[2] = {sb + 32768, sb + 40960};

    const int tid = threadIdx.x, lane = tid & 31, wid = tid >> 5;
    const int wm = wid & 3, wn = wid >> 2;

    auto load = [&](int kt) {
        int buf = kt & 1;
#pragma unroll
        for (int p = 0; p < 4; p++) {
            int idx = p * 256 + tid, r = idx >> 3, kc = idx & 7;
            CP16(swz(sA[buf], 128, r, kc), &A[(size_t)(m0 + r) * EMB + kt * 64 + kc * 8]);
        }
#pragma unroll
        for (int p = 0; p < 2; p++) {
            int idx = p * 256 + tid, r = idx >> 3, kc = idx & 7;
            CP16(swz(sB[buf], 128, r, kc), &B[(size_t)(n0 + r) * EMB + kt * 64 + kc * 8]);
        }
    };

    float acc[2][4][4] = {};
    load(0); CP_COMMIT();

    for (int kt = 0; kt < 8; kt++) {
        if (kt < 7) { load(kt + 1); CP_COMMIT(); CP_WAITN(1); }
        else        { CP_WAITN(0); }
        __syncthreads();
        const uint32_t a0 = sA[kt & 1], b0 = sB[kt & 1];
#pragma unroll
        for (int s = 0; s < 4; s++) {               // k16 steps
            uint32_t af[2][4], bf[2][4];
#pragma unroll
            for (int mf = 0; mf < 2; mf++)
                ldsm4(af[mf], fragAddr(a0, 128, wm * 32 + mf * 16, s * 2, lane));
#pragma unroll
            for (int p = 0; p < 2; p++)
                ldsm4(bf[p], fragAddr(b0, 128, wn * 32 + p * 16, s * 2, lane));
#pragma unroll
            for (int mf = 0; mf < 2; mf++)
#pragma unroll
                for (int p = 0; p < 2; p++) {
                    mma16(acc[mf][2 * p],     af[mf], bf[p][0], bf[p][2]);
                    mma16(acc[mf][2 * p + 1], af[mf], bf[p][1], bf[p][3]);
                }
        }
        __syncthreads();
    }

#pragma unroll
    for (int mf = 0; mf < 2; mf++) {
        int r0 = m0 + wm * 32 + mf * 16 + (lane >> 2);
#pragma unroll
        for (int nf = 0; nf < 4; nf++) {
            int col = n0 + wn * 32 + nf * 8 + 2 * (lane & 3);
            float v0 = acc[mf][nf][0] * scale, v1 = acc[mf][nf][1] * scale;
            float v2 = acc[mf][nf][2] * scale, v3 = acc[mf][nf][3] * scale;
            if (mode == 0) {                         // half, row-major
                __half* C = (__half*)Cout;
                *(uint32_t*)&C[(size_t)r0 * EMB + col]       = packh2(v0, v1);
                *(uint32_t*)&C[(size_t)(r0 + 8) * EMB + col] = packh2(v2, v3);
            } else if (mode == 1) {                  // half, transposed (Vt)
                __half* C = (__half*)Cout;
                C[(size_t)col * T_SEQ + r0]           = __float2half_rn(v0);
                C[(size_t)(col + 1) * T_SEQ + r0]     = __float2half_rn(v1);
                C[(size_t)col * T_SEQ + r0 + 8]       = __float2half_rn(v2);
                C[(size_t)(col + 1) * T_SEQ + r0 + 8] = __float2half_rn(v3);
            } else {                                 // fp32 final output
                float* C = (float*)Cout;
                *(float2*)&C[(size_t)r0 * EMB + col]       = make_float2(v0, v1);
                *(float2*)&C[(size_t)(r0 + 8) * EMB + col] = make_float2(v2, v3);
            }
        }
    }
}

// Fused QKV: blockIdx.x: [0,8) -> Q, [8,16) -> K, [16,24) -> V(transposed out)
__global__ __launch_bounds__(256, 2) void qkv_gemm(const __half* __restrict__ A,
                                                   const __half* __restrict__ W,
                                                   __half* __restrict__ Cq,
                                                   __half* __restrict__ Ck,
                                                   __half* __restrict__ Cv) {
    extern __shared__ __align__(1024) char sm[];
    int which = blockIdx.x >> 3;
    int n0 = (blockIdx.x & 7) * 64;
    int m0 = blockIdx.y * 128;
    const __half* B = W + (size_t)which * EMB * EMB;
    __half* C = (which == 0) ? Cq : (which == 1) ? Ck : Cv;
    float scale = (which == 0) ? QSCALE : 1.0f;
    gemm_body(A, B, C, scale, (which == 2) ? 1 : 0, m0, n0, sm);
}

__global__ __launch_bounds__(256, 2) void gemm_out(const __half* __restrict__ A,
                                                   const __half* __restrict__ B,
                                                   float* __restrict__ C) {
    extern __shared__ __align__(1024) char sm[];
    gemm_body(A, B, C, 1.0f, 2, blockIdx.y * 128, blockIdx.x * 64, sm);
}

// ----------------------------------------------------------------- attention
// CTA: 128 q x 1 head, 64 key tiles of 64 keys, 256 thr, 2 CTAs/SM.
// Each warp owns 16 q-rows across ALL keys: no k-split, no cross-warp
// reduction, l is warp-local. P never leaves registers (lane-local fp16 pack).
// K and V double-buffered. smem: Q 16K | K dbl 16K | V dbl 16K = 48K.
#define ASMEM 49152
__global__ __launch_bounds__(256, 2) void attn_tc(const __half* __restrict__ Q,
                                                  const __half* __restrict__ K,
                                                  const __half* __restrict__ Vt,
                                                  __half* __restrict__ O) {
    extern __shared__ __align__(1024) char sm[];
    const uint32_t sb = s2u(sm);
    const uint32_t sQ = sb;
    const uint32_t sK[2] = {sb + 16384, sb + 24576};
    const uint32_t sV[2] = {sb + 32768, sb + 40960};

    const int tid = threadIdx.x, lane = tid & 31, wid = tid >> 5;
    const int h = blockIdx.y, q0 = blockIdx.x * 128;

    auto loadK = [&](int t) {
        int k0 = t * 64;
        uint32_t base = sK[t & 1];
#pragma unroll
        for (int p = 0; p < 2; p++) {
            int idx = p * 256 + tid, r = idx >> 3, kc = idx & 7;
            CP16(swz(base, 128, r, kc), &K[(size_t)(k0 + r) * EMB + h * HDIM + kc * 8]);
        }
    };
    auto loadV = [&](int t) {
        uint32_t base = sV[t & 1];
#pragma unroll
        for (int p = 0; p < 2; p++) {
            int idx = p * 256 + tid, r = idx >> 3, kc = idx & 7;
            CP16(swz(base, 128, r, kc), &Vt[(size_t)(h * HDIM + r) * T_SEQ + t * 64 + kc * 8]);
        }
    };

    // prologue: {Q, K0} group, {V0} group
#pragma unroll
    for (int p = 0; p < 4; p++) {
        int idx = p * 256 + tid, r = idx >> 3, kc = idx & 7;
        CP16(swz(sQ, 128, r, kc), &Q[(size_t)(q0 + r) * EMB + h * HDIM + kc * 8]);
    }
    loadK(0); CP_COMMIT();
    loadV(0); CP_COMMIT();
    CP_WAITN(1);               // Q, K0 resident
    __syncthreads();

    // register-cache Q fragments: m16 x k64 per warp = 16 regs
    uint32_t qf[4][4];
#pragma unroll
    for (int s = 0; s < 4; s++)
        ldsm4(qf[s], fragAddr(sQ, 128, wid * 16, s * 2, lane));

    float oacc[8][4] = {};
    float la0 = 0.0f, la1 = 0.0f;

    for (int t = 0; t < 64; t++) {
        if (t < 63) {
            loadK(t + 1); CP_COMMIT();
            loadV(t + 1); CP_COMMIT();
            CP_WAITN(2);       // K(t), V(t) resident
        } else {
            CP_WAITN(0);
        }
        __syncthreads();

        // --- S = Q K(t)^T over all 64 keys (log2 domain) ---
        float sacc[8][4] = {};
        const uint32_t kb = sK[t & 1];
#pragma unroll
        for (int s = 0; s < 4; s++) {
            uint32_t kf[4][4];
#pragma unroll
            for (int nb = 0; nb < 4; nb++)
                ldsm4(kf[nb], fragAddr(kb, 128, nb * 16, s * 2, lane));
#pragma unroll
            for (int nb = 0; nb < 4; nb++) {
                mma16(sacc[2 * nb],     qf[s], kf[nb][0], kf[nb][2]);
                mma16(sacc[2 * nb + 1], qf[s], kf[nb][1], kf[nb][3]);
            }
        }

        // --- P = 2^S -> fp16 A-frags (lane-local pack); warp-local l ---
        uint32_t aP[4][4];
        float r0s = 0.0f, r1s = 0.0f;
#pragma unroll
        for (int nf = 0; nf < 8; nf++) {
            float e0 = ex2f(sacc[nf][0]);
            float e1 = ex2f(sacc[nf][1]);
            float e2 = ex2f(sacc[nf][2]);
            float e3 = ex2f(sacc[nf][3]);
            r0s += e0 + e1;
            r1s += e2 + e3;
            int ks = nf >> 1, hi = (nf & 1) * 2;
            aP[ks][hi]     = packh2(e0, e1);
            aP[ks][hi + 1] = packh2(e2, e3);
        }
        la0 += r0s;
        la1 += r1s;

        // --- O += P V(t) over all 64 keys ---
        const uint32_t vb = sV[t & 1];
#pragma unroll
        for (int ks = 0; ks < 4; ks++) {
            uint32_t bf[4][4];
#pragma unroll
            for (int p = 0; p < 4; p++)
                ldsm4(bf[p], fragAddr(vb, 128, p * 16, ks * 2, lane));
#pragma unroll
            for (int p = 0; p < 4; p++) {
                mma16(oacc[2 * p],     aP[ks], bf[p][0], bf[p][2]);
                mma16(oacc[2 * p + 1], aP[ks], bf[p][1], bf[p][3]);
            }
        }
        __syncthreads();       // K/V buffer reuse safe
    }

    // --- warp-local l reduction (quad), then O /= l, store fp16 ---
    la0 += __shfl_xor_sync(0xffffffffu, la0, 1);
    la0 += __shfl_xor_sync(0xffffffffu, la0, 2);
    la1 += __shfl_xor_sync(0xffffffffu, la1, 1);
    la1 += __shfl_xor_sync(0xffffffffu, la1, 2);
    float li0 = 1.0f / la0;
    float li1 = 1.0f / la1;

    int r = wid * 16 + (lane >> 2);
#pragma unroll
    for (int df = 0; df < 8; df++) {
        int col = df * 8 + 2 * (lane & 3);
        *(uint32_t*)&O[(size_t)(q0 + r) * EMB + h * HDIM + col] =
            packh2(oacc[df][0] * li0, oacc[df][1] * li0);
        *(uint32_t*)&O[(size_t)(q0 + r + 8) * EMB + h * HDIM + col] =
            packh2(oacc[df][2] * li1, oacc[df][3] * li1);
    }
}

// ----------------------------------------------------------------- launch
extern "C" void kernel_launch(void* const* d_in, const int* in_sizes, int n_in,
                              void* d_out, int out_size) {
    const float* x  = (const float*)d_in[0];
    const float* wq = (const float*)d_in[1];
    const float* wk = (const float*)d_in[2];
    const float* wv = (const float*)d_in[3];
    const float* wo = (const float*)d_in[4];
    float* out = (float*)d_out;

    __half *px, *pw, *pQ, *pK, *pVt, *pA;
    cudaGetSymbolAddress((void**)&px, g_x);
    cudaGetSymbolAddress((void**)&pw, g_w);
    cudaGetSymbolAddress((void**)&pQ, g_Q);
    cudaGetSymbolAddress((void**)&pK, g_K);
    cudaGetSymbolAddress((void**)&pVt, g_Vt);
    cudaGetSymbolAddress((void**)&pA, g_att);

    cudaFuncSetAttribute(qkv_gemm, cudaFuncAttributeMaxDynamicSharedMemorySize, GSM);
    cudaFuncSetAttribute(gemm_out, cudaFuncAttributeMaxDynamicSharedMemorySize, GSM);
    cudaFuncSetAttribute(attn_tc, cudaFuncAttributeMaxDynamicSharedMemorySize, ASMEM);

    round_all<<<3072, 256>>>(x, wq, wk, wv, wo, px, pw);

    qkv_gemm<<<dim3(24, 32), 256, GSM>>>(px, pw, pQ, pK, pVt);

    dim3 ga(T_SEQ / 128, NHEAD);       // (32, 8)
    attn_tc<<<ga, 256, ASMEM>>>(pQ, pK, pVt, pA);

    gemm_out<<<dim3(8, 32), 256, GSM>>>(pA, pw + 3 * (size_t)EMB * EMB, out);
}